// round 3
// baseline (speedup 1.0000x reference)
#include <cuda_runtime.h>

// Problem constants
#define B       8
#define C       64
#define G       8
#define FPG     8
#define OCPG    8
#define KS      3
#define REPD    32
#define H       256
#define Wd      256
#define PLANE   (H * Wd)             // 65536
#define PLANE4  (PLANE / 4)          // 16384
#define NWTS    (OCPG * KS * KS)     // 72

// Tile config for conv kernel
#define TX      64
#define TY      32
#define NTHR    256
#define HALO_W  66                   // logical halo width
#define HALO_P  68                   // padded row stride (16B aligned)
#define HALO_H  34

// Channel-summed planes: [B][G][H][W] = 16.8 MB scratch
__device__ __align__(16) float g_S[B * G * PLANE];

// ---------------------------------------------------------------------------
// Kernel 1: channel sum. S[b,g,:] = sum_{ch<8} x[b, g*8+ch, :]
// Pure streaming, float4, MLP=8.
// ---------------------------------------------------------------------------
__global__ __launch_bounds__(256)
void chansum(const float* __restrict__ x) {
    const int idx = blockIdx.x * 256 + threadIdx.x;    // float4 index
    const int bg  = idx >> 14;                          // / PLANE4
    const int off = idx & (PLANE4 - 1);
    const int b   = bg >> 3;
    const int g   = bg & 7;

    const float4* xb = (const float4*)x
                     + ((size_t)(b * C + g * FPG)) * PLANE4 + off;
    float4 s = xb[0];
#pragma unroll
    for (int ch = 1; ch < FPG; ++ch) {
        const float4 v = xb[(size_t)ch * PLANE4];
        s.x += v.x; s.y += v.y; s.z += v.z; s.w += v.w;
    }
    ((float4*)g_S)[idx] = s;
}

// ---------------------------------------------------------------------------
// Kernel 2: per-block weight gen + 3x3 dynamic conv over channel-summed S.
// grid: (W/TX, H/TY, B*G), block 256.
// Thread = (x-quad q, output channel oc, y-half ys): 4 cols x 16 rows x 1 oc.
// ---------------------------------------------------------------------------
__global__ __launch_bounds__(NTHR, 4)
void dyn_conv(const float* __restrict__ rep,
              const float* __restrict__ Wm,
              float* __restrict__ out) {
    const int bg = blockIdx.z;
    const int b  = bg >> 3;
    const int g  = bg & 7;
    const int x0 = blockIdx.x * TX;
    const int y0 = blockIdx.y * TY;
    const int t  = threadIdx.x;

    __shared__ __align__(16) float S[HALO_H * HALO_P];
    __shared__ float wsh[NWTS];
    __shared__ float rsh[REPD];

    // ---- weight generation (W matrix is small & L2-resident) ----
    if (t < REPD) rsh[t] = rep[b * REPD + t];
    __syncthreads();
    if (t < NWTS) {
        const float* wrow = Wm + (size_t)(g * NWTS + t) * REPD;
        float acc = 0.f;
#pragma unroll
        for (int j = 0; j < REPD; ++j) acc = fmaf(rsh[j], wrow[j], acc);
        wsh[t] = acc > 0.f ? acc : 0.1f * acc;
    }

    // ---- Phase 1: load halo tile of S (1 load per element, mostly L2) ----
    const float* Sg = g_S + (size_t)bg * PLANE;
    for (int idx = t; idx < HALO_H * HALO_W; idx += NTHR) {
        const int r = idx / HALO_W;
        const int c = idx - r * HALO_W;
        int yy = y0 - 1 + r;
        yy = (yy < 0) ? -yy : yy;
        yy = (yy >= H) ? (2 * H - 2 - yy) : yy;
        int xx = x0 - 1 + c;
        xx = (xx < 0) ? -xx : xx;
        xx = (xx >= Wd) ? (2 * Wd - 2 - xx) : xx;
        S[r * HALO_P + c] = Sg[yy * Wd + xx];
    }
    __syncthreads();

    // ---- Phase 2: 3x3 conv. 4 cols (float4 store) x 16 rows x 1 oc ----
    const int q  = t & 15;            // x-quad: cols 4q..4q+3
    const int oc = (t >> 4) & 7;      // output channel within group
    const int ys = t >> 7;            // 0/1: rows 0-15 / 16-31

    float w[9];
#pragma unroll
    for (int k = 0; k < 9; ++k) w[k] = wsh[oc * 9 + k];

    const int hx = q * 4;             // halo col of leftmost tap
    const int hy = ys * 16;           // first halo row of window top

    float4* optr = (float4*)(out + ((size_t)(b * C + g * OCPG + oc)) * PLANE
                                 + (size_t)(y0 + hy) * Wd + x0) + q;

    // 6-wide sliding window rows (a = top, m = mid)
    float a0,a1,a2,a3,a4,a5, m0,m1,m2,m3,m4,m5;
    {
        const float4 v4 = *(const float4*)&S[hy * HALO_P + hx];
        const float2 v2 = *(const float2*)&S[hy * HALO_P + hx + 4];
        a0=v4.x; a1=v4.y; a2=v4.z; a3=v4.w; a4=v2.x; a5=v2.y;
    }
    {
        const float4 v4 = *(const float4*)&S[(hy+1) * HALO_P + hx];
        const float2 v2 = *(const float2*)&S[(hy+1) * HALO_P + hx + 4];
        m0=v4.x; m1=v4.y; m2=v4.z; m3=v4.w; m4=v2.x; m5=v2.y;
    }

#pragma unroll
    for (int r = 0; r < 16; ++r) {
        const float4 v4 = *(const float4*)&S[(hy + r + 2) * HALO_P + hx];
        const float2 v2 = *(const float2*)&S[(hy + r + 2) * HALO_P + hx + 4];
        const float c0=v4.x, c1=v4.y, c2=v4.z, c3=v4.w, c4=v2.x, c5=v2.y;

        float4 o;
        o.x =      w[0]*a0;           o.y =      w[0]*a1;
        o.x = fmaf(w[1],a1,o.x);      o.y = fmaf(w[1],a2,o.y);
        o.x = fmaf(w[2],a2,o.x);      o.y = fmaf(w[2],a3,o.y);
        o.x = fmaf(w[3],m0,o.x);      o.y = fmaf(w[3],m1,o.y);
        o.x = fmaf(w[4],m1,o.x);      o.y = fmaf(w[4],m2,o.y);
        o.x = fmaf(w[5],m2,o.x);      o.y = fmaf(w[5],m3,o.y);
        o.x = fmaf(w[6],c0,o.x);      o.y = fmaf(w[6],c1,o.y);
        o.x = fmaf(w[7],c1,o.x);      o.y = fmaf(w[7],c2,o.y);
        o.x = fmaf(w[8],c2,o.x);      o.y = fmaf(w[8],c3,o.y);

        o.z =      w[0]*a2;           o.w =      w[0]*a3;
        o.z = fmaf(w[1],a3,o.z);      o.w = fmaf(w[1],a4,o.w);
        o.z = fmaf(w[2],a4,o.z);      o.w = fmaf(w[2],a5,o.w);
        o.z = fmaf(w[3],m2,o.z);      o.w = fmaf(w[3],m3,o.w);
        o.z = fmaf(w[4],m3,o.z);      o.w = fmaf(w[4],m4,o.w);
        o.z = fmaf(w[5],m4,o.z);      o.w = fmaf(w[5],m5,o.w);
        o.z = fmaf(w[6],c2,o.z);      o.w = fmaf(w[6],c3,o.w);
        o.z = fmaf(w[7],c3,o.z);      o.w = fmaf(w[7],c4,o.w);
        o.z = fmaf(w[8],c4,o.z);      o.w = fmaf(w[8],c5,o.w);

        optr[(size_t)r * (Wd / 4)] = o;

        a0=m0; a1=m1; a2=m2; a3=m3; a4=m4; a5=m5;
        m0=c0; m1=c1; m2=c2; m3=c3; m4=c4; m5=c5;
    }
}

// ---------------------------------------------------------------------------
extern "C" void kernel_launch(void* const* d_in, const int* in_sizes, int n_in,
                              void* d_out, int out_size) {
    const float* x   = (const float*)d_in[0];
    const float* rep = (const float*)d_in[1];
    const float* Wm  = (const float*)d_in[2];
    float* out = (float*)d_out;

    chansum<<<(B * G * PLANE4) / 256, 256>>>(x);

    dim3 grid(Wd / TX, H / TY, B * G);
    dyn_conv<<<grid, NTHR>>>(rep, Wm, out);
}

// round 4
// speedup vs baseline: 1.5207x; 1.5207x over previous
#include <cuda_runtime.h>

// Problem constants
#define B       8
#define C       64
#define G       8
#define FPG     8
#define OCPG    8
#define REPD    32
#define H       256
#define Wd      256
#define PLANE   (H * Wd)             // 65536
#define PLANE4  (PLANE / 4)          // 16384
#define NWTS    (OCPG * 9)           // 72

// Tile: full image width x 16 rows
#define TY      16
#define NTHR    256
#define SROWS   (TY + 2)             // 18
#define SSTR    260                  // floats per smem row (16B aligned, 65 float4)
#define SSTR4   (SSTR / 4)

// ---------------------------------------------------------------------------
// Fused kernel: weight-gen + channel-sum (reflect pad) + 3x3 dynamic conv.
// grid: (H/TY, B*G), block 256.
// Phase 2: thread = (x-quad q, oc-pair {p, p+4}), 16 rows sliding window.
// ---------------------------------------------------------------------------
__global__ __launch_bounds__(NTHR, 4)
void dyn_conv(const float* __restrict__ x,
              const float* __restrict__ rep,
              const float* __restrict__ Wm,
              float* __restrict__ out) {
    const int bg = blockIdx.y;
    const int b  = bg >> 3;
    const int g  = bg & 7;
    const int y0 = blockIdx.x * TY;
    const int t  = threadIdx.x;

    __shared__ __align__(16) float S[SROWS * SSTR];
    __shared__ float wsh[NWTS];
    __shared__ float rsh[REPD];

    // ---- weight generation (tiny; W is L2-resident) ----
    if (t < REPD) rsh[t] = rep[b * REPD + t];
    __syncthreads();
    if (t < NWTS) {
        const float* wrow = Wm + (size_t)(g * NWTS + t) * REPD;
        float acc = 0.f;
#pragma unroll
        for (int j = 0; j < REPD; ++j) acc = fmaf(rsh[j], wrow[j], acc);
        wsh[t] = acc > 0.f ? acc : 0.1f * acc;
    }

    // ---- Phase 1: channel-sum 18 full-width rows into smem (all float4) ----
    const float4* xb = (const float4*)x + ((size_t)(b * C + g * FPG)) * PLANE4;
#pragma unroll
    for (int idx = t; idx < SROWS * 64; idx += NTHR) {   // 1152 float4s
        const int r  = idx >> 6;
        const int q4 = idx & 63;
        int yy = y0 - 1 + r;
        yy = (yy < 0) ? -yy : yy;
        yy = (yy >= H) ? (2 * H - 2 - yy) : yy;
        const float4* p = xb + (size_t)yy * 64 + q4;
        float4 s = p[0];
#pragma unroll
        for (int ch = 1; ch < FPG; ++ch) {
            const float4 v = p[(size_t)ch * PLANE4];
            s.x += v.x; s.y += v.y; s.z += v.z; s.w += v.w;
        }
        ((float4*)S)[r * SSTR4 + q4] = s;
    }
    __syncthreads();

    // ---- Phase 2: 3x3 conv, 2 output channels (p, p+4), 16 rows ----
    const int q  = t & 63;            // x-quad: output cols 4q..4q+3
    const int p  = t >> 6;            // 0..3 -> channels p and p+4

    float w0[9], w1[9];
#pragma unroll
    for (int k = 0; k < 9; ++k) {
        w0[k] = wsh[p * 9 + k];
        w1[k] = wsh[(p + 4) * 9 + k];
    }

    // reflect-remapped edge-tap columns
    const int cL = (q == 0)  ? 1   : 4 * q - 1;
    const int cR = (q == 63) ? 254 : 4 * q + 4;

    float4* o0 = (float4*)(out + ((size_t)(b * C + g * OCPG + p)) * PLANE
                               + (size_t)y0 * Wd) + q;
    float4* o1 = o0 + 4 * PLANE4;     // channel p+4

    // sliding 6-wide window rows: a = top, m = mid
    float a0,a1,a2,a3,a4,a5, m0,m1,m2,m3,m4,m5;
    {
        const float4 v = *(const float4*)&S[0 * SSTR + 4 * q];
        a0 = S[0 * SSTR + cL]; a1 = v.x; a2 = v.y; a3 = v.z; a4 = v.w; a5 = S[0 * SSTR + cR];
    }
    {
        const float4 v = *(const float4*)&S[1 * SSTR + 4 * q];
        m0 = S[1 * SSTR + cL]; m1 = v.x; m2 = v.y; m3 = v.z; m4 = v.w; m5 = S[1 * SSTR + cR];
    }

#pragma unroll
    for (int r = 0; r < TY; ++r) {
        const float4 v = *(const float4*)&S[(r + 2) * SSTR + 4 * q];
        const float c0 = S[(r + 2) * SSTR + cL];
        const float c1 = v.x, c2 = v.y, c3 = v.z, c4 = v.w;
        const float c5 = S[(r + 2) * SSTR + cR];

        float4 u, s;
        u.x =      w0[0]*a0;          s.x =      w1[0]*a0;
        u.x = fmaf(w0[1],a1,u.x);     s.x = fmaf(w1[1],a1,s.x);
        u.x = fmaf(w0[2],a2,u.x);     s.x = fmaf(w1[2],a2,s.x);
        u.x = fmaf(w0[3],m0,u.x);     s.x = fmaf(w1[3],m0,s.x);
        u.x = fmaf(w0[4],m1,u.x);     s.x = fmaf(w1[4],m1,s.x);
        u.x = fmaf(w0[5],m2,u.x);     s.x = fmaf(w1[5],m2,s.x);
        u.x = fmaf(w0[6],c0,u.x);     s.x = fmaf(w1[6],c0,s.x);
        u.x = fmaf(w0[7],c1,u.x);     s.x = fmaf(w1[7],c1,s.x);
        u.x = fmaf(w0[8],c2,u.x);     s.x = fmaf(w1[8],c2,s.x);

        u.y =      w0[0]*a1;          s.y =      w1[0]*a1;
        u.y = fmaf(w0[1],a2,u.y);     s.y = fmaf(w1[1],a2,s.y);
        u.y = fmaf(w0[2],a3,u.y);     s.y = fmaf(w1[2],a3,s.y);
        u.y = fmaf(w0[3],m1,u.y);     s.y = fmaf(w1[3],m1,s.y);
        u.y = fmaf(w0[4],m2,u.y);     s.y = fmaf(w1[4],m2,s.y);
        u.y = fmaf(w0[5],m3,u.y);     s.y = fmaf(w1[5],m3,s.y);
        u.y = fmaf(w0[6],c1,u.y);     s.y = fmaf(w1[6],c1,s.y);
        u.y = fmaf(w0[7],c2,u.y);     s.y = fmaf(w1[7],c2,s.y);
        u.y = fmaf(w0[8],c3,u.y);     s.y = fmaf(w1[8],c3,s.y);

        u.z =      w0[0]*a2;          s.z =      w1[0]*a2;
        u.z = fmaf(w0[1],a3,u.z);     s.z = fmaf(w1[1],a3,s.z);
        u.z = fmaf(w0[2],a4,u.z);     s.z = fmaf(w1[2],a4,s.z);
        u.z = fmaf(w0[3],m2,u.z);     s.z = fmaf(w1[3],m2,s.z);
        u.z = fmaf(w0[4],m3,u.z);     s.z = fmaf(w1[4],m3,s.z);
        u.z = fmaf(w0[5],m4,u.z);     s.z = fmaf(w1[5],m4,s.z);
        u.z = fmaf(w0[6],c2,u.z);     s.z = fmaf(w1[6],c2,s.z);
        u.z = fmaf(w0[7],c3,u.z);     s.z = fmaf(w1[7],c3,s.z);
        u.z = fmaf(w0[8],c4,u.z);     s.z = fmaf(w1[8],c4,s.z);

        u.w =      w0[0]*a3;          s.w =      w1[0]*a3;
        u.w = fmaf(w0[1],a4,u.w);     s.w = fmaf(w1[1],a4,s.w);
        u.w = fmaf(w0[2],a5,u.w);     s.w = fmaf(w1[2],a5,s.w);
        u.w = fmaf(w0[3],m3,u.w);     s.w = fmaf(w1[3],m3,s.w);
        u.w = fmaf(w0[4],m4,u.w);     s.w = fmaf(w1[4],m4,s.w);
        u.w = fmaf(w0[5],m5,u.w);     s.w = fmaf(w1[5],m5,s.w);
        u.w = fmaf(w0[6],c3,u.w);     s.w = fmaf(w1[6],c3,s.w);
        u.w = fmaf(w0[7],c4,u.w);     s.w = fmaf(w1[7],c4,s.w);
        u.w = fmaf(w0[8],c5,u.w);     s.w = fmaf(w1[8],c5,s.w);

        o0[(size_t)r * 64] = u;
        o1[(size_t)r * 64] = s;

        a0=m0; a1=m1; a2=m2; a3=m3; a4=m4; a5=m5;
        m0=c0; m1=c1; m2=c2; m3=c3; m4=c4; m5=c5;
    }
}

// ---------------------------------------------------------------------------
extern "C" void kernel_launch(void* const* d_in, const int* in_sizes, int n_in,
                              void* d_out, int out_size) {
    const float* x   = (const float*)d_in[0];
    const float* rep = (const float*)d_in[1];
    const float* Wm  = (const float*)d_in[2];
    float* out = (float*)d_out;

    dim3 grid(H / TY, B * G);
    dyn_conv<<<grid, NTHR>>>(x, rep, Wm, out);
}